// round 5
// baseline (speedup 1.0000x reference)
#include <cuda_runtime.h>
#include <cstdint>

#define TT 100
#define BB 1024
#define NIN 784
#define NHID 1000
#define NOUT 10

// Eigen gebp k-blocking: k_cache = min((L1-ksub)/kdiv, 320) -> 320 on real HW
#define KC 320

// cur1 scratch [T, B, NHID] = 409.6 MB
__device__ float g_cur1[(size_t)TT * BB * NHID];

// ---------------------------------------------------------------------------
// Kernel A: cur1[m,n] = ((P0+P1)+P2) + b1[n],  P_i = fma chain over k-panel i
// (Eigen gebp association, kc=320). fp32, 128x128 tile, 8x8 microtile.
// ---------------------------------------------------------------------------
#define BM 128
#define BN 128
#define BK 8

__global__ void __launch_bounds__(256, 1) gemm_cur1_kernel(
    const float* __restrict__ X,   // [M=T*B, K]
    const float* __restrict__ W1,  // [NHID, K]
    const float* __restrict__ b1)  // [NHID]
{
    __shared__ float As[BK][BM];
    __shared__ float Bs[BK][BN];

    const int tid = threadIdx.x;
    const int tx = tid & 15;        // n
    const int ty = tid >> 4;        // m
    const int m0 = blockIdx.y * BM;
    const int n0 = blockIdx.x * BN;

    const int lrow = tid >> 1;           // 0..127
    const int lcol = (tid & 1) * 4;      // 0 or 4

    const float* Aptr = X  + (size_t)(m0 + lrow) * NIN + lcol;
    const float* Bptr = W1 + (size_t)(n0 + lrow) * NIN + lcol;
    const bool bvalid = (n0 + lrow) < NHID;

    float c[8][8];    // committed across panels
#pragma unroll
    for (int i = 0; i < 8; ++i)
#pragma unroll
        for (int j = 0; j < 8; ++j) c[i][j] = 0.f;

    for (int p0 = 0; p0 < NIN; p0 += KC) {
        const int pend = (p0 + KC < NIN) ? (p0 + KC) : NIN;

        float pa[8][8];   // panel accumulator (chain restarts at 0)
#pragma unroll
        for (int i = 0; i < 8; ++i)
#pragma unroll
            for (int j = 0; j < 8; ++j) pa[i][j] = 0.f;

        for (int k0 = p0; k0 < pend; k0 += BK) {
            float4 av = *(const float4*)(Aptr + k0);
            float4 bv = bvalid ? *(const float4*)(Bptr + k0)
                               : make_float4(0.f, 0.f, 0.f, 0.f);
            __syncthreads();
            As[lcol + 0][lrow] = av.x;
            As[lcol + 1][lrow] = av.y;
            As[lcol + 2][lrow] = av.z;
            As[lcol + 3][lrow] = av.w;
            Bs[lcol + 0][lrow] = bv.x;
            Bs[lcol + 1][lrow] = bv.y;
            Bs[lcol + 2][lrow] = bv.z;
            Bs[lcol + 3][lrow] = bv.w;
            __syncthreads();

#pragma unroll
            for (int k = 0; k < BK; ++k) {
                float a[8], b[8];
#pragma unroll
                for (int i = 0; i < 8; ++i) a[i] = As[k][ty * 8 + i];
#pragma unroll
                for (int j = 0; j < 8; ++j) b[j] = Bs[k][tx * 8 + j];
#pragma unroll
                for (int i = 0; i < 8; ++i)
#pragma unroll
                    for (int j = 0; j < 8; ++j)
                        pa[i][j] = __fmaf_rn(a[i], b[j], pa[i][j]);
            }
        }

        // Eigen: C_mem += panel  (separate fp32 rounding per panel commit)
#pragma unroll
        for (int i = 0; i < 8; ++i)
#pragma unroll
            for (int j = 0; j < 8; ++j) c[i][j] = __fadd_rn(c[i][j], pa[i][j]);
    }

#pragma unroll
    for (int i = 0; i < 8; ++i) {
        const size_t row = (size_t)(m0 + ty * 8 + i) * NHID;
#pragma unroll
        for (int j = 0; j < 8; ++j) {
            const int n = n0 + tx * 8 + j;
            if (n < NHID) g_cur1[row + n] = __fadd_rn(c[i][j], b1[n]);
        }
    }
}

// ---------------------------------------------------------------------------
// Kernel B: LIF recurrence, one block per batch row, 256 threads.
// Layer 1: strict separately-rounded elementwise (XLA):
//   m = ((0.9*mem) + cur) - reset ; spike = m > 1
// Layer 2: threads 0..9: sequential fma dot with the SAME kc=320 panel
//   association over K=1000, bias added last.
// ---------------------------------------------------------------------------
__global__ void __launch_bounds__(256) lif_kernel(
    const float* __restrict__ W2,   // [NOUT, NHID]
    const float* __restrict__ b2,   // [NOUT]
    float* __restrict__ out)
{
    const int b   = blockIdx.x;
    const int tid = threadIdx.x;
    const int h0  = tid * 4;
    const bool act = (h0 < NHID);

    __shared__ float spk1s[NHID];
    __shared__ float W2s[NOUT * NHID];   // 40 KB

    for (int i = tid; i < NOUT * NHID; i += 256) W2s[i] = W2[i];

    float mem1[4] = {0.f, 0.f, 0.f, 0.f};
    float rst1[4] = {0.f, 0.f, 0.f, 0.f};

    float mem2 = 0.f, rst2 = 0.f, b2v = 0.f;
    if (tid < NOUT) b2v = b2[tid];

    const size_t stride = (size_t)BB * NHID;
    const float* base = g_cur1 + (size_t)b * NHID + h0;

    float4 cv = act ? *(const float4*)(base) : make_float4(0, 0, 0, 0);
    __syncthreads();

    for (int t = 0; t < TT; ++t) {
        float4 nv = make_float4(0, 0, 0, 0);
        if (act && (t + 1 < TT)) nv = *(const float4*)(base + (size_t)(t + 1) * stride);

        if (act) {
            float c4[4] = {cv.x, cv.y, cv.z, cv.w};
#pragma unroll
            for (int j = 0; j < 4; ++j) {
                float m = __fsub_rn(__fadd_rn(__fmul_rn(0.9f, mem1[j]), c4[j]), rst1[j]);
                float s = (m > 1.0f) ? 1.0f : 0.0f;
                mem1[j] = m;
                rst1[j] = s;
                spk1s[h0 + j] = s;
            }
        }
        __syncthreads();

        if (tid < NOUT) {
            // kc=320 panel association over h = 0..999
            float acc = 0.f;
            const float* wrow = &W2s[tid * NHID];
            for (int p0 = 0; p0 < NHID; p0 += KC) {
                const int pend = (p0 + KC < NHID) ? (p0 + KC) : NHID;
                float pacc = 0.f;
#pragma unroll 8
                for (int h = p0; h < pend; ++h)
                    pacc = __fmaf_rn(spk1s[h], wrow[h], pacc);
                acc = __fadd_rn(acc, pacc);
            }
            float c2 = __fadd_rn(acc, b2v);   // bias last, separate rounding
            float m2 = __fsub_rn(__fadd_rn(__fmul_rn(0.9f, mem2), c2), rst2);
            float s2 = (m2 > 1.0f) ? 1.0f : 0.0f;
            mem2 = m2;
            rst2 = s2;
            const size_t idx = ((size_t)t * BB + b) * NOUT + tid;
            out[idx] = s2;
            out[(size_t)TT * BB * NOUT + idx] = m2;
        }
        __syncthreads();
        cv = nv;
    }
}

// ---------------------------------------------------------------------------
extern "C" void kernel_launch(void* const* d_in, const int* in_sizes, int n_in,
                              void* d_out, int out_size)
{
    const float* x  = (const float*)d_in[0];
    const float* W1 = (const float*)d_in[1];
    const float* b1 = (const float*)d_in[2];
    const float* W2 = (const float*)d_in[3];
    const float* b2 = (const float*)d_in[4];
    float* out = (float*)d_out;

    dim3 grid((NHID + BN - 1) / BN, (TT * BB) / BM);   // (8, 800)
    gemm_cur1_kernel<<<grid, 256>>>(x, W1, b1);

    lif_kernel<<<BB, 256>>>(W2, b2, out);
}

// round 6
// speedup vs baseline: 1.3437x; 1.3437x over previous
#include <cuda_runtime.h>
#include <cstdint>

#define TT 100
#define BB 1024
#define NIN 784
#define NHID 1000
#define NOUT 10

// Eigen gebp k-blocking (validated R5): kc = 320
#define KC 320

// cur1 scratch [T, B, NHID] = 409.6 MB
__device__ float g_cur1[(size_t)TT * BB * NHID];

// ---------------------------------------------------------------------------
// Kernel A: cur1[m,n] = ((P0+P1)+P2) + b1[n],  P_i = fma chain over k-panel i
// (kc=320 association). fp32 FFMA, 128x128 tile, 8x8 microtile,
// double-buffered smem + register prefetch, ONE sync per k-step.
// ---------------------------------------------------------------------------
#define BM 128
#define BN 128
#define BK 8
#define PADR 132              // padded smem row (floats): conflict-free STS
#define NITER (NIN / BK)      // 98

__global__ void __launch_bounds__(256, 1) gemm_cur1_kernel(
    const float* __restrict__ X,   // [M=T*B, K]
    const float* __restrict__ W1,  // [NHID, K]
    const float* __restrict__ b1)  // [NHID]
{
    __shared__ float As[2][BK][PADR];
    __shared__ float Bs[2][BK][PADR];

    const int tid = threadIdx.x;
    const int tx = tid & 15;        // n
    const int ty = tid >> 4;        // m
    const int m0 = blockIdx.y * BM;
    const int n0 = blockIdx.x * BN;

    const int lrow = tid >> 1;           // 0..127
    const int lcol = (tid & 1) * 4;      // 0 or 4

    const float* Aptr = X  + (size_t)(m0 + lrow) * NIN + lcol;
    const float* Bptr = W1 + (size_t)(n0 + lrow) * NIN + lcol;
    const bool bvalid = (n0 + lrow) < NHID;

    float c[8][8];    // committed across panels
#pragma unroll
    for (int i = 0; i < 8; ++i)
#pragma unroll
        for (int j = 0; j < 8; ++j) c[i][j] = 0.f;

    float pa[8][8];   // panel accumulator

    // prologue: stage 0
    {
        float4 av = *(const float4*)(Aptr);
        float4 bv = bvalid ? *(const float4*)(Bptr) : make_float4(0, 0, 0, 0);
        As[0][lcol + 0][lrow] = av.x;
        As[0][lcol + 1][lrow] = av.y;
        As[0][lcol + 2][lrow] = av.z;
        As[0][lcol + 3][lrow] = av.w;
        Bs[0][lcol + 0][lrow] = bv.x;
        Bs[0][lcol + 1][lrow] = bv.y;
        Bs[0][lcol + 2][lrow] = bv.z;
        Bs[0][lcol + 3][lrow] = bv.w;
    }
    __syncthreads();

    int buf = 0;
#pragma unroll 1
    for (int it = 0; it < NITER; ++it) {
        // panel start: zero the panel accumulator
        if (it == 0 || it == 40 || it == 80) {
#pragma unroll
            for (int i = 0; i < 8; ++i)
#pragma unroll
                for (int j = 0; j < 8; ++j) pa[i][j] = 0.f;
        }

        // prefetch next k-slice into registers (overlaps with compute)
        const bool notlast = (it < NITER - 1);
        float4 nav = make_float4(0, 0, 0, 0), nbv = make_float4(0, 0, 0, 0);
        if (notlast) {
            nav = *(const float4*)(Aptr + (it + 1) * BK);
            if (bvalid) nbv = *(const float4*)(Bptr + (it + 1) * BK);
        }

        // compute on current buffer
#pragma unroll
        for (int k = 0; k < BK; ++k) {
            float a[8], b[8];
            *(float4*)(a)     = *(const float4*)(&As[buf][k][ty * 8]);
            *(float4*)(a + 4) = *(const float4*)(&As[buf][k][ty * 8 + 4]);
            *(float4*)(b)     = *(const float4*)(&Bs[buf][k][tx * 8]);
            *(float4*)(b + 4) = *(const float4*)(&Bs[buf][k][tx * 8 + 4]);
#pragma unroll
            for (int i = 0; i < 8; ++i)
#pragma unroll
                for (int j = 0; j < 8; ++j)
                    pa[i][j] = __fmaf_rn(a[i], b[j], pa[i][j]);
        }

        // panel end: commit with a separate fp32 rounding (Eigen C += panel)
        if (it == 39 || it == 79 || it == NITER - 1) {
#pragma unroll
            for (int i = 0; i < 8; ++i)
#pragma unroll
                for (int j = 0; j < 8; ++j) c[i][j] = __fadd_rn(c[i][j], pa[i][j]);
        }

        if (notlast) {
            const int nb = buf ^ 1;
            As[nb][lcol + 0][lrow] = nav.x;
            As[nb][lcol + 1][lrow] = nav.y;
            As[nb][lcol + 2][lrow] = nav.z;
            As[nb][lcol + 3][lrow] = nav.w;
            Bs[nb][lcol + 0][lrow] = nbv.x;
            Bs[nb][lcol + 1][lrow] = nbv.y;
            Bs[nb][lcol + 2][lrow] = nbv.z;
            Bs[nb][lcol + 3][lrow] = nbv.w;
            __syncthreads();
            buf = nb;
        }
    }

#pragma unroll
    for (int i = 0; i < 8; ++i) {
        const size_t row = (size_t)(m0 + ty * 8 + i) * NHID;
#pragma unroll
        for (int j = 0; j < 8; ++j) {
            const int n = n0 + tx * 8 + j;
            if (n < NHID) g_cur1[row + n] = __fadd_rn(c[i][j], b1[n]);
        }
    }
}

// ---------------------------------------------------------------------------
// Kernel B: LIF recurrence, one block per batch row, 256 threads.
// Thread tid owns hidden units h = i*256 + tid (i=0..3) so warp ballots give
// contiguous ascending 32-bit spike mask words. Layer-2 dot walks SET BITS
// only (fma(0,w,acc)==acc exactly) in ascending h with kc=320 panel breaks at
// word 10 and word 20 -- bitwise identical to the dense chain.
// ---------------------------------------------------------------------------
__global__ void __launch_bounds__(256) lif_kernel(
    const float* __restrict__ W2,   // [NOUT, NHID]
    const float* __restrict__ b2,   // [NOUT]
    float* __restrict__ out)
{
    const int b    = blockIdx.x;
    const int tid  = threadIdx.x;
    const int warp = tid >> 5, lane = tid & 31;

    __shared__ float    W2s[NOUT * NHID];   // 40 KB
    __shared__ uint32_t masks[32];

    for (int i = tid; i < NOUT * NHID; i += 256) W2s[i] = W2[i];

    float mem1[4] = {0.f, 0.f, 0.f, 0.f};
    uint32_t rstb = 0;   // 4 reset bits (this thread's units)

    float mem2 = 0.f, rst2 = 0.f, b2v = 0.f;
    if (tid < NOUT) b2v = b2[tid];

    const float* cr0 = g_cur1 + (size_t)b * NHID;
    const size_t tstride = (size_t)BB * NHID;

    // preload t=0 currents
    float cv[4];
#pragma unroll
    for (int i = 0; i < 4; ++i) {
        const int h = i * 256 + tid;
        cv[i] = (h < NHID) ? __ldg(cr0 + h) : 0.f;
    }
    __syncthreads();

    for (int t = 0; t < TT; ++t) {
        // layer 1 update + ballot masks
        uint32_t nrst = 0;
#pragma unroll
        for (int i = 0; i < 4; ++i) {
            const int h = i * 256 + tid;
            const float rstv = ((rstb >> i) & 1u) ? 1.f : 0.f;
            const float m = __fsub_rn(__fadd_rn(__fmul_rn(0.9f, mem1[i]), cv[i]), rstv);
            mem1[i] = m;
            const bool s = (m > 1.0f) && (h < NHID);
            const uint32_t bal = __ballot_sync(0xffffffffu, s);
            if (lane == 0) masks[i * 8 + warp] = bal;
            if (s) nrst |= (1u << i);
        }
        rstb = nrst;

        // prefetch next step's currents (overlaps dot + syncs)
        float nv[4] = {0.f, 0.f, 0.f, 0.f};
        if (t + 1 < TT) {
            const float* crn = cr0 + (size_t)(t + 1) * tstride;
#pragma unroll
            for (int i = 0; i < 4; ++i) {
                const int h = i * 256 + tid;
                if (h < NHID) nv[i] = __ldg(crn + h);
            }
        }
        __syncthreads();

        if (tid < NOUT) {
            const float* wrow = &W2s[tid * NHID];
            float acc = 0.f;
            // panels: words [0,10) [10,20) [20,32)  (h: 0..319, 320..639, 640..999)
#pragma unroll
            for (int p = 0; p < 3; ++p) {
                const int w0 = p * 10;
                const int w1 = (p == 2) ? 32 : w0 + 10;
                float pacc = 0.f;
                for (int w = w0; w < w1; ++w) {
                    uint32_t m = masks[w];
                    const float* wb = wrow + w * 32;
                    while (m) {
                        const int bi = __ffs(m) - 1;
                        pacc = __fadd_rn(pacc, wb[bi]);
                        m &= m - 1;
                    }
                }
                acc = __fadd_rn(acc, pacc);
            }
            const float c2 = __fadd_rn(acc, b2v);
            const float m2 = __fsub_rn(__fadd_rn(__fmul_rn(0.9f, mem2), c2), rst2);
            const float s2 = (m2 > 1.0f) ? 1.0f : 0.0f;
            mem2 = m2;
            rst2 = s2;
            const size_t idx = ((size_t)t * BB + b) * NOUT + tid;
            out[idx] = s2;
            out[(size_t)TT * BB * NOUT + idx] = m2;
        }
        __syncthreads();
#pragma unroll
        for (int i = 0; i < 4; ++i) cv[i] = nv[i];
    }
}

// ---------------------------------------------------------------------------
extern "C" void kernel_launch(void* const* d_in, const int* in_sizes, int n_in,
                              void* d_out, int out_size)
{
    const float* x  = (const float*)d_in[0];
    const float* W1 = (const float*)d_in[1];
    const float* b1 = (const float*)d_in[2];
    const float* W2 = (const float*)d_in[3];
    const float* b2 = (const float*)d_in[4];
    float* out = (float*)d_out;

    dim3 grid((NHID + BN - 1) / BN, (TT * BB) / BM);   // (8, 800)
    gemm_cur1_kernel<<<grid, 256>>>(x, W1, b1);

    lif_kernel<<<BB, 256>>>(W2, b2, out);
}